// round 2
// baseline (speedup 1.0000x reference)
#include <cuda_runtime.h>
#include <cuda_bf16.h>

// Problem constants
#define Bc 2
#define Nc 96
#define NNc 9216            // Nc*Nc
#define Dc 64
#define Hc 4
#define DKc 16
#define ROWS_TOTAL 18432    // Bc*NNc

typedef unsigned long long u64;

// ---- packed f32x2 helpers (Blackwell FFMA2 path; ptxas won't emit from C++) ----
#define FMA2(d, a, b, c) asm("fma.rn.f32x2 %0, %1, %2, %3;" : "=l"(d) : "l"(a), "l"(b), "l"(c))
#define MUL2(d, a, b)    asm("mul.rn.f32x2 %0, %1, %2;"     : "=l"(d) : "l"(a), "l"(b))
#define ADD2(d, a, b)    asm("add.rn.f32x2 %0, %1, %2;"     : "=l"(d) : "l"(a), "l"(b))
#define PACK2(d, lo, hi) asm("mov.b64 %0, {%1, %2};"        : "=l"(d) : "f"(lo), "f"(hi))
#define UNPACK2(lo, hi, d) asm("mov.b64 {%0, %1}, %2;"      : "=f"(lo), "=f"(hi) : "l"(d))

// Scratch (device globals; allocation-free per harness rules)
// g_proj layout: [proj(4)][b(2)][h(4)][i(9216)][d(16)]
__device__ float g_proj[4u * Bc * Hc * NNc * DKc];   // 18.9 MB
__device__ float g_attout[(size_t)ROWS_TOTAL * Dc];  // 4.7 MB

// ---------------------------------------------------------------------------
// Kernel A: fused 4-way projection.  out256[row][p] = state[row][:] @ W_p^T + b
// Block: 256 threads, 32 rows.  Weights transposed in smem, state duplicated
// as (s,s) pairs so the f32x2 splat is a single LDS.64 broadcast.
// ---------------------------------------------------------------------------
#define A_WS_STRIDE 260   // padded stride for w_s[k][pcol]  (float4-aligned)

__global__ void __launch_bounds__(256)
proj_kernel(const float* __restrict__ state,
            const float* __restrict__ w_lk, const float* __restrict__ b_lk,
            const float* __restrict__ w_rk, const float* __restrict__ b_rk,
            const float* __restrict__ w_lv, const float* __restrict__ b_lv,
            const float* __restrict__ w_rv, const float* __restrict__ b_rv)
{
    extern __shared__ __align__(16) float smem[];
    float* w_s   = smem;                       // 64 * 260 = 16640 floats
    float* st2_s = smem + 64 * A_WS_STRIDE;    // 32 * 64 * 2 = 4096 floats (dup)
    float* bias_s = st2_s + 4096;              // 256 floats

    const int tid = threadIdx.x;
    const int rowBase = blockIdx.x * 32;

    // Load weights transposed: w_s[k][proj*64 + p] = W_proj[p][k]
#pragma unroll
    for (int proj = 0; proj < 4; ++proj) {
        const float* W = (proj == 0) ? w_lk : (proj == 1) ? w_rk
                        : (proj == 2) ? w_lv : w_rv;
        for (int idx = tid; idx < 4096; idx += 256) {
            int p = idx >> 6, k = idx & 63;
            w_s[k * A_WS_STRIDE + proj * 64 + p] = W[idx];
        }
    }
    {
        const float* bsrc = (tid < 64) ? b_lk : (tid < 128) ? b_rk
                           : (tid < 192) ? b_lv : b_rv;
        bias_s[tid] = bsrc[tid & 63];
    }
    // Duplicated state tile: st2[(r*64+k)] = (s, s)
    for (int i = tid; i < 2048; i += 256) {
        float v = state[(size_t)rowBase * 64 + i];
        ((float2*)st2_s)[i] = make_float2(v, v);
    }
    __syncthreads();

    const int pg = (tid & 63) * 4;   // output column group (0..252, step 4)
    const int r0 = (tid >> 6) * 8;   // row group within tile

    u64 acc[8][2];
#pragma unroll
    for (int i = 0; i < 8; ++i) { acc[i][0] = 0ull; acc[i][1] = 0ull; }

#pragma unroll 8
    for (int k = 0; k < 64; ++k) {
        ulonglong2 wq = *(const ulonglong2*)&w_s[k * A_WS_STRIDE + pg];
#pragma unroll
        for (int i = 0; i < 8; ++i) {
            u64 s2 = *(const u64*)&st2_s[((r0 + i) * 64 + k) * 2];
            FMA2(acc[i][0], s2, wq.x, acc[i][0]);
            FMA2(acc[i][1], s2, wq.y, acc[i][1]);
        }
    }

    const float4 bv = *(const float4*)&bias_s[pg];
    u64 b01, b23;
    PACK2(b01, bv.x, bv.y);
    PACK2(b23, bv.z, bv.w);

    const int proj = pg >> 6;
    const int h    = (pg >> 4) & 3;
    const int d    = pg & 15;

#pragma unroll
    for (int i = 0; i < 8; ++i) {
        int row = rowBase + r0 + i;
        int b   = row / NNc;
        int idx = row - b * NNc;
        ulonglong2 v;
        ADD2(v.x, acc[i][0], b01);
        ADD2(v.y, acc[i][1], b23);
        size_t off = ((size_t)((proj * Bc + b) * Hc + h) * NNc + idx) * DKc + d;
        *(ulonglong2*)&g_proj[off] = v;
    }
}

// ---------------------------------------------------------------------------
// Kernel B: scores + softmax(a) + triple-product contraction.
// Block per (b, h, x-tile of 4).  y processed in quarters of 24.
// smem = 86.4 KB -> 2 blocks/SM, grid 192 -> single resident wave.
// ---------------------------------------------------------------------------
#define TXc 4
#define YHc 24

__global__ void __launch_bounds__(384, 2)
attn_kernel()
{
    extern __shared__ __align__(16) float smem[];
    float* lk_s = smem;                 // TX * 96 * 16 = 6144
    float* lv_s = smem + 6144;          // 6144
    float* sc   = smem + 12288;         // TX * 96 * 24 = 9216
    float* linv = smem + 21504;         // 96

    const int tid = threadIdx.x;
    const int xt = blockIdx.x % (Nc / TXc);
    const int bh = blockIdx.x / (Nc / TXc);
    const int h  = bh % Hc;
    const int b  = bh / Hc;
    const int x0 = xt * TXc;

    const int slab = NNc * DKc;  // 147456
    const float* lkbase = g_proj + (size_t)((0 * Bc + b) * Hc + h) * slab;
    const float* rkbase = g_proj + (size_t)((1 * Bc + b) * Hc + h) * slab;
    const float* lvbase = g_proj + (size_t)((2 * Bc + b) * Hc + h) * slab;
    const float* rvbase = g_proj + (size_t)((3 * Bc + b) * Hc + h) * slab;

    // Phase 1: load lk / lv for x0..x0+3 (contiguous 6144 floats each)
    {
        const float4* slk = (const float4*)(lkbase + (size_t)x0 * 1536);
        const float4* slv = (const float4*)(lvbase + (size_t)x0 * 1536);
        float4* dlk = (float4*)lk_s;
        float4* dlv = (float4*)lv_s;
        for (int i = tid; i < 1536; i += 384) {
            dlk[i] = slk[i];
            dlv[i] = slv[i];
        }
    }
    __syncthreads();

    for (int yh = 0; yh < 96; yh += YHc) {
        // ---- Phase 2: scores[tx][a][yl] = (lk_x[a,:] . rk[a,y,:]) * 0.25
#pragma unroll 2
        for (int idx = tid; idx < 96 * YHc; idx += 384) {
            int a  = idx / YHc;
            int yl = idx - a * YHc;
            int y  = yh + yl;
            const ulonglong2* rp = (const ulonglong2*)(rkbase + (size_t)(a * 96 + y) * 16);
            ulonglong2 q0 = rp[0], q1 = rp[1], q2 = rp[2], q3 = rp[3];
#pragma unroll
            for (int tx = 0; tx < TXc; ++tx) {
                const ulonglong2* lp = (const ulonglong2*)(lk_s + tx * 1536 + a * 16);
                ulonglong2 l0 = lp[0], l1 = lp[1], l2 = lp[2], l3 = lp[3];
                u64 t;
                MUL2(t, l0.x, q0.x);
                FMA2(t, l0.y, q0.y, t);
                FMA2(t, l1.x, q1.x, t);
                FMA2(t, l1.y, q1.y, t);
                FMA2(t, l2.x, q2.x, t);
                FMA2(t, l2.y, q2.y, t);
                FMA2(t, l3.x, q3.x, t);
                FMA2(t, l3.y, q3.y, t);
                float lo, hi;
                UNPACK2(lo, hi, t);
                sc[tx * 96 * YHc + a * YHc + yl] = (lo + hi) * 0.25f;
            }
        }
        __syncthreads();

        // ---- Softmax over a (unnormalized exp; keep 1/sum)
        if (tid < TXc * YHc) {
            int tx = tid / YHc;
            int yl = tid - tx * YHc;
            float* col = sc + tx * 96 * YHc + yl;
            float m = -1e30f;
#pragma unroll 4
            for (int a = 0; a < 96; ++a) m = fmaxf(m, col[a * YHc]);
            float l = 0.f;
#pragma unroll 4
            for (int a = 0; a < 96; ++a) {
                float e = __expf(col[a * YHc] - m);
                col[a * YHc] = e;
                l += e;
            }
            linv[tid] = 1.f / l;
        }
        __syncthreads();

        // ---- Phase 3: out[tx][y][d] = (1/l) * sum_a e[a,y]*lv[a,d]*rv[a,y,d]
        {
            int dq = tid & 3;
            int yl = (tid >> 2) % YHc;
            int tx = tid / (YHc * 4);
            int y  = yh + yl;
            u64 acc0 = 0ull, acc1 = 0ull;
#pragma unroll 4
            for (int a = 0; a < 96; ++a) {
                ulonglong2 rv = *(const ulonglong2*)(rvbase + (size_t)(a * 96 + y) * 16 + dq * 4);
                float w = sc[tx * 96 * YHc + a * YHc + yl];
                u64 w2;
                PACK2(w2, w, w);
                ulonglong2 v = *(const ulonglong2*)(lv_s + tx * 1536 + a * 16 + dq * 4);
                u64 t0, t1;
                MUL2(t0, v.x, rv.x);
                MUL2(t1, v.y, rv.y);
                FMA2(acc0, w2, t0, acc0);
                FMA2(acc1, w2, t1, acc1);
            }
            float s = linv[tx * YHc + yl];
            u64 s2;
            PACK2(s2, s, s);
            ulonglong2 o;
            MUL2(o.x, acc0, s2);
            MUL2(o.y, acc1, s2);
            size_t row = (size_t)b * NNc + (size_t)(x0 + tx) * 96 + y;
            *(ulonglong2*)&g_attout[row * 64 + h * 16 + dq * 4] = o;
        }
        __syncthreads();
    }
}

// ---------------------------------------------------------------------------
// Kernel C: output projection.  out[i][p] = attout[i][:] @ w_out^T + b_out
// Block: 256 threads, 64 rows per block.  f32x2 with duplicated state.
// ---------------------------------------------------------------------------
#define C_WS_STRIDE 68

__global__ void __launch_bounds__(256)
out_kernel(const float* __restrict__ w_out, const float* __restrict__ b_out,
           float* __restrict__ out)
{
    extern __shared__ __align__(16) float smem[];
    float* w_s   = smem;                        // 64 * 68 = 4352 floats
    float* st2_s = smem + 64 * C_WS_STRIDE;     // 64 * 64 * 2 = 8192 floats
    float* bias_s = st2_s + 8192;               // 64 floats

    const int tid = threadIdx.x;
    const int rowBase = blockIdx.x * 64;

    for (int idx = tid; idx < 4096; idx += 256) {
        int p = idx >> 6, k = idx & 63;
        w_s[k * C_WS_STRIDE + p] = w_out[idx];
    }
    if (tid < 64) bias_s[tid] = b_out[tid];
    for (int i = tid; i < 4096; i += 256) {
        float v = g_attout[(size_t)rowBase * 64 + i];
        ((float2*)st2_s)[i] = make_float2(v, v);
    }
    __syncthreads();

    const int p0 = (tid & 15) * 4;
    const int r0 = (tid >> 4) * 4;

    u64 acc[4][2];
#pragma unroll
    for (int i = 0; i < 4; ++i) { acc[i][0] = 0ull; acc[i][1] = 0ull; }

#pragma unroll 8
    for (int k = 0; k < 64; ++k) {
        ulonglong2 wq = *(const ulonglong2*)&w_s[k * C_WS_STRIDE + p0];
#pragma unroll
        for (int i = 0; i < 4; ++i) {
            u64 s2 = *(const u64*)&st2_s[((r0 + i) * 64 + k) * 2];
            FMA2(acc[i][0], s2, wq.x, acc[i][0]);
            FMA2(acc[i][1], s2, wq.y, acc[i][1]);
        }
    }

    const float4 bv = *(const float4*)&bias_s[p0];
    u64 b01, b23;
    PACK2(b01, bv.x, bv.y);
    PACK2(b23, bv.z, bv.w);

#pragma unroll
    for (int i = 0; i < 4; ++i) {
        int row = rowBase + r0 + i;
        ulonglong2 v;
        ADD2(v.x, acc[i][0], b01);
        ADD2(v.y, acc[i][1], b23);
        *(ulonglong2*)&out[(size_t)row * 64 + p0] = v;
    }
}

// ---------------------------------------------------------------------------
extern "C" void kernel_launch(void* const* d_in, const int* in_sizes, int n_in,
                              void* d_out, int out_size)
{
    const float* state = (const float*)d_in[0];
    const float* w_lk = (const float*)d_in[1];
    const float* b_lk = (const float*)d_in[2];
    const float* w_rk = (const float*)d_in[3];
    const float* b_rk = (const float*)d_in[4];
    const float* w_lv = (const float*)d_in[5];
    const float* b_lv = (const float*)d_in[6];
    const float* w_rv = (const float*)d_in[7];
    const float* b_rv = (const float*)d_in[8];
    const float* w_out = (const float*)d_in[9];
    const float* b_out = (const float*)d_in[10];
    float* out = (float*)d_out;

    const int smemA = (64 * A_WS_STRIDE + 4096 + 256) * 4;        // 83968 B
    const int smemB = (6144 + 6144 + 9216 + 96) * 4;              // 86400 B
    const int smemC = (64 * C_WS_STRIDE + 8192 + 64) * 4;         // 50432 B

    static bool attr_done = false;
    if (!attr_done) {
        cudaFuncSetAttribute(proj_kernel,
                             cudaFuncAttributeMaxDynamicSharedMemorySize, smemA);
        cudaFuncSetAttribute(attn_kernel,
                             cudaFuncAttributeMaxDynamicSharedMemorySize, smemB);
        cudaFuncSetAttribute(out_kernel,
                             cudaFuncAttributeMaxDynamicSharedMemorySize, smemC);
        attr_done = true;
    }

    proj_kernel<<<ROWS_TOTAL / 32, 256, smemA>>>(
        state, w_lk, b_lk, w_rk, b_rk, w_lv, b_lv, w_rv, b_rv);

    attn_kernel<<<Bc * Hc * (Nc / TXc), 384, smemB>>>();

    out_kernel<<<ROWS_TOTAL / 64, 256, smemC>>>(w_out, b_out, out);
}

// round 3
// speedup vs baseline: 1.2276x; 1.2276x over previous
#include <cuda_runtime.h>
#include <cuda_bf16.h>

// Problem constants
#define Bc 2
#define Nc 96
#define NNc 9216            // Nc*Nc
#define Dc 64
#define Hc 4
#define DKc 16
#define ROWS_TOTAL 18432    // Bc*NNc

// Scratch (device globals; allocation-free per harness rules)
// g_proj layout: [proj(4)][b(2)][h(4)][i(9216)][d(16)]
__device__ float g_proj[4u * Bc * Hc * NNc * DKc];   // 18.9 MB
__device__ float g_attout[(size_t)ROWS_TOTAL * Dc];  // 4.7 MB

// ---------------------------------------------------------------------------
// Kernel A: projection, one projection per blockIdx.y.
// Block: 256 threads, 64 rows x 64 cols of one projection.
// smem = 34 KB -> 6 blocks/SM resident (75% occ).
// ---------------------------------------------------------------------------
#define A_WS_STRIDE 68

__global__ void __launch_bounds__(256)
proj_kernel(const float* __restrict__ state,
            const float* __restrict__ w_lk, const float* __restrict__ b_lk,
            const float* __restrict__ w_rk, const float* __restrict__ b_rk,
            const float* __restrict__ w_lv, const float* __restrict__ b_lv,
            const float* __restrict__ w_rv, const float* __restrict__ b_rv)
{
    __shared__ __align__(16) float w_s[64 * A_WS_STRIDE];
    __shared__ __align__(16) float st_s[64 * 64];
    __shared__ float bias_s[64];

    const int tid = threadIdx.x;
    const int rowBase = blockIdx.x * 64;
    const int proj = blockIdx.y;

    const float* W = (proj == 0) ? w_lk : (proj == 1) ? w_rk
                    : (proj == 2) ? w_lv : w_rv;
    const float* Bv = (proj == 0) ? b_lk : (proj == 1) ? b_rk
                     : (proj == 2) ? b_lv : b_rv;

    // Weights transposed: w_s[k][p] = W[p][k]
    for (int idx = tid; idx < 4096; idx += 256) {
        int p = idx >> 6, k = idx & 63;
        w_s[k * A_WS_STRIDE + p] = W[idx];
    }
    if (tid < 64) bias_s[tid] = Bv[tid];
    {
        const float4* src = (const float4*)(state + (size_t)rowBase * 64);
        float4* dst = (float4*)st_s;
        for (int i = tid; i < 1024; i += 256) dst[i] = src[i];
    }
    __syncthreads();

    const int p0 = (tid & 15) * 4;   // output column group
    const int r0 = (tid >> 4) * 4;   // row group

    float acc[4][4];
#pragma unroll
    for (int i = 0; i < 4; ++i)
#pragma unroll
        for (int j = 0; j < 4; ++j) acc[i][j] = 0.f;

#pragma unroll 8
    for (int k = 0; k < 64; ++k) {
        float4 wv = *(const float4*)&w_s[k * A_WS_STRIDE + p0];
#pragma unroll
        for (int i = 0; i < 4; ++i) {
            float s = st_s[(r0 + i) * 64 + k];
            acc[i][0] += s * wv.x;
            acc[i][1] += s * wv.y;
            acc[i][2] += s * wv.z;
            acc[i][3] += s * wv.w;
        }
    }

    const float4 bv = *(const float4*)&bias_s[p0];
    const int h = p0 >> 4;
    const int d = p0 & 15;

#pragma unroll
    for (int i = 0; i < 4; ++i) {
        int row = rowBase + r0 + i;
        int b   = row / NNc;
        int idx = row - b * NNc;
        float4 v;
        v.x = acc[i][0] + bv.x;
        v.y = acc[i][1] + bv.y;
        v.z = acc[i][2] + bv.z;
        v.w = acc[i][3] + bv.w;
        size_t off = ((size_t)((proj * Bc + b) * Hc + h) * NNc + idx) * DKc + d;
        *(float4*)&g_proj[off] = v;
    }
}

// ---------------------------------------------------------------------------
// Kernel B: scores + softmax(a) + triple-product contraction.
// Block per (b, h, x-tile of 3).  y processed in thirds of 32.
// smem = 74.1 KB -> 3 blocks/SM, grid 256 -> single resident wave.
// ---------------------------------------------------------------------------
#define TXc 3
#define YHc 32

__global__ void __launch_bounds__(384, 3)
attn_kernel()
{
    extern __shared__ __align__(16) float smem[];
    float* lk_s = smem;                 // TX * 96 * 16 = 4608
    float* lv_s = smem + 4608;          // 4608
    float* sc   = smem + 9216;          // TX * 96 * 32 = 9216
    float* linv = smem + 18432;         // 96

    const int tid = threadIdx.x;
    const int xt = blockIdx.x % (Nc / TXc);
    const int bh = blockIdx.x / (Nc / TXc);
    const int h  = bh % Hc;
    const int b  = bh / Hc;
    const int x0 = xt * TXc;

    const int slab = NNc * DKc;  // 147456
    const float* lkbase = g_proj + (size_t)((0 * Bc + b) * Hc + h) * slab;
    const float* rkbase = g_proj + (size_t)((1 * Bc + b) * Hc + h) * slab;
    const float* lvbase = g_proj + (size_t)((2 * Bc + b) * Hc + h) * slab;
    const float* rvbase = g_proj + (size_t)((3 * Bc + b) * Hc + h) * slab;

    // Phase 1: load lk / lv for x0..x0+2 (contiguous 4608 floats each)
    {
        const float4* slk = (const float4*)(lkbase + (size_t)x0 * 1536);
        const float4* slv = (const float4*)(lvbase + (size_t)x0 * 1536);
        float4* dlk = (float4*)lk_s;
        float4* dlv = (float4*)lv_s;
        for (int i = tid; i < 1152; i += 384) {
            dlk[i] = slk[i];
            dlv[i] = slv[i];
        }
    }
    __syncthreads();

    for (int yh = 0; yh < 96; yh += YHc) {
        // ---- Phase 2: scores[tx][a][yl] = (lk_x[a,:] . rk[a,y,:]) * 0.25
#pragma unroll
        for (int j = 0; j < (96 * YHc) / 384; ++j) {
            int idx = tid + j * 384;
            int a  = idx >> 5;
            int yl = idx & 31;
            int y  = yh + yl;
            const float4* rp = (const float4*)(rkbase + (size_t)(a * 96 + y) * 16);
            float4 q0 = rp[0], q1 = rp[1], q2 = rp[2], q3 = rp[3];
#pragma unroll
            for (int tx = 0; tx < TXc; ++tx) {
                const float4* lp = (const float4*)(lk_s + tx * 1536 + a * 16);
                float4 l0 = lp[0], l1 = lp[1], l2 = lp[2], l3 = lp[3];
                float s0 = l0.x * q0.x + l0.y * q0.y + l0.z * q0.z + l0.w * q0.w;
                float s1 = l1.x * q1.x + l1.y * q1.y + l1.z * q1.z + l1.w * q1.w;
                float s2 = l2.x * q2.x + l2.y * q2.y + l2.z * q2.z + l2.w * q2.w;
                float s3 = l3.x * q3.x + l3.y * q3.y + l3.z * q3.z + l3.w * q3.w;
                sc[tx * 96 * YHc + a * YHc + yl] = (s0 + s1 + s2 + s3) * 0.25f;
            }
        }
        __syncthreads();

        // ---- Softmax over a (unnormalized exp; keep 1/sum)
        if (tid < TXc * YHc) {
            int tx = tid >> 5;
            int yl = tid & 31;
            float* col = sc + tx * 96 * YHc + yl;
            float m = -1e30f;
#pragma unroll 4
            for (int a = 0; a < 96; ++a) m = fmaxf(m, col[a * YHc]);
            float l = 0.f;
#pragma unroll 4
            for (int a = 0; a < 96; ++a) {
                float e = __expf(col[a * YHc] - m);
                col[a * YHc] = e;
                l += e;
            }
            linv[tid] = 1.f / l;
        }
        __syncthreads();

        // ---- Phase 3: out[tx][y][d] = (1/l) * sum_a e[a,y]*lv[a,d]*rv[a,y,d]
        {
            int dq = tid & 3;
            int yl = (tid >> 2) & 31;
            int tx = tid >> 7;       // 0..2
            int y  = yh + yl;
            float4 acc = {0.f, 0.f, 0.f, 0.f};
#pragma unroll 4
            for (int a = 0; a < 96; ++a) {
                float4 rv = *(const float4*)(rvbase + (size_t)(a * 96 + y) * 16 + dq * 4);
                float w = sc[tx * 96 * YHc + a * YHc + yl];
                float4 v = *(const float4*)(lv_s + tx * 1536 + a * 16 + dq * 4);
                acc.x += w * (v.x * rv.x);
                acc.y += w * (v.y * rv.y);
                acc.z += w * (v.z * rv.z);
                acc.w += w * (v.w * rv.w);
            }
            float s = linv[tx * YHc + yl];
            acc.x *= s; acc.y *= s; acc.z *= s; acc.w *= s;
            size_t row = (size_t)b * NNc + (size_t)(x0 + tx) * 96 + y;
            *(float4*)&g_attout[row * 64 + h * 16 + dq * 4] = acc;
        }
        __syncthreads();
    }
}

// ---------------------------------------------------------------------------
// Kernel C: output projection.  out[i][p] = attout[i][:] @ w_out^T + b_out
// Block: 256 threads, 64 rows per block.
// ---------------------------------------------------------------------------
#define C_WS_STRIDE 68

__global__ void __launch_bounds__(256)
out_kernel(const float* __restrict__ w_out, const float* __restrict__ b_out,
           float* __restrict__ out)
{
    __shared__ __align__(16) float w_s[64 * C_WS_STRIDE];
    __shared__ __align__(16) float st_s[64 * 64];
    __shared__ float bias_s[64];

    const int tid = threadIdx.x;
    const int rowBase = blockIdx.x * 64;

    for (int idx = tid; idx < 4096; idx += 256) {
        int p = idx >> 6, k = idx & 63;
        w_s[k * C_WS_STRIDE + p] = w_out[idx];
    }
    if (tid < 64) bias_s[tid] = b_out[tid];
    {
        const float4* src = (const float4*)(g_attout + (size_t)rowBase * 64);
        float4* dst = (float4*)st_s;
        for (int i = tid; i < 1024; i += 256) dst[i] = src[i];
    }
    __syncthreads();

    const int p0 = (tid & 15) * 4;
    const int r0 = (tid >> 4) * 4;

    float acc[4][4];
#pragma unroll
    for (int i = 0; i < 4; ++i)
#pragma unroll
        for (int j = 0; j < 4; ++j) acc[i][j] = 0.f;

#pragma unroll 8
    for (int k = 0; k < 64; ++k) {
        float4 wv = *(const float4*)&w_s[k * C_WS_STRIDE + p0];
#pragma unroll
        for (int i = 0; i < 4; ++i) {
            float s = st_s[(r0 + i) * 64 + k];
            acc[i][0] += s * wv.x;
            acc[i][1] += s * wv.y;
            acc[i][2] += s * wv.z;
            acc[i][3] += s * wv.w;
        }
    }

    const float4 bv = *(const float4*)&bias_s[p0];
#pragma unroll
    for (int i = 0; i < 4; ++i) {
        int row = rowBase + r0 + i;
        float4 v;
        v.x = acc[i][0] + bv.x;
        v.y = acc[i][1] + bv.y;
        v.z = acc[i][2] + bv.z;
        v.w = acc[i][3] + bv.w;
        *(float4*)&out[(size_t)row * 64 + p0] = v;
    }
}

// ---------------------------------------------------------------------------
extern "C" void kernel_launch(void* const* d_in, const int* in_sizes, int n_in,
                              void* d_out, int out_size)
{
    const float* state = (const float*)d_in[0];
    const float* w_lk = (const float*)d_in[1];
    const float* b_lk = (const float*)d_in[2];
    const float* w_rk = (const float*)d_in[3];
    const float* b_rk = (const float*)d_in[4];
    const float* w_lv = (const float*)d_in[5];
    const float* b_lv = (const float*)d_in[6];
    const float* w_rv = (const float*)d_in[7];
    const float* b_rv = (const float*)d_in[8];
    const float* w_out = (const float*)d_in[9];
    const float* b_out = (const float*)d_in[10];
    float* out = (float*)d_out;

    const int smemB = (4608 + 4608 + 9216 + 96) * 4;  // 74112 B

    static bool attr_done = false;
    if (!attr_done) {
        cudaFuncSetAttribute(attn_kernel,
                             cudaFuncAttributeMaxDynamicSharedMemorySize, smemB);
        attr_done = true;
    }

    dim3 gridA(ROWS_TOTAL / 64, 4);
    proj_kernel<<<gridA, 256>>>(
        state, w_lk, b_lk, w_rk, b_rk, w_lv, b_lv, w_rv, b_rv);

    attn_kernel<<<Bc * Hc * (Nc / TXc), 384, smemB>>>();

    out_kernel<<<ROWS_TOTAL / 64, 256>>>(w_out, b_out, out);
}

// round 4
// speedup vs baseline: 1.4928x; 1.2161x over previous
#include <cuda_runtime.h>
#include <cuda_bf16.h>

// Problem constants
#define Bc 2
#define Nc 96
#define NNc 9216            // Nc*Nc
#define Dc 64
#define Hc 4
#define DKc 16
#define ROWS_TOTAL 18432    // Bc*NNc

// Scratch (device globals; allocation-free per harness rules)
// g_proj layout: [proj(4)][b(2)][h(4)][i(9216)][d(16)]  (rk slot unused)
__device__ float g_proj[4u * Bc * Hc * NNc * DKc];          // 18.9 MB
// rk transposed: [b][h][a(96)][d(16)][y(96)]
__device__ float g_rkT[(size_t)Bc * Hc * Nc * DKc * Nc];    // 4.7 MB
__device__ float g_attout[(size_t)ROWS_TOTAL * Dc];         // 4.7 MB

// ---------------------------------------------------------------------------
// Kernel A: projection, one projection per blockIdx.y.
// proj==1 (rk) is written TRANSPOSED into g_rkT for coalesced attn reads.
// ---------------------------------------------------------------------------
#define A_WS_STRIDE 68

__global__ void __launch_bounds__(256)
proj_kernel(const float* __restrict__ state,
            const float* __restrict__ w_lk, const float* __restrict__ b_lk,
            const float* __restrict__ w_rk, const float* __restrict__ b_rk,
            const float* __restrict__ w_lv, const float* __restrict__ b_lv,
            const float* __restrict__ w_rv, const float* __restrict__ b_rv)
{
    __shared__ __align__(16) float w_s[64 * A_WS_STRIDE];
    __shared__ __align__(16) float st_s[64 * 64];
    __shared__ float bias_s[64];

    const int tid = threadIdx.x;
    const int rowBase = blockIdx.x * 64;
    const int proj = blockIdx.y;

    const float* W = (proj == 0) ? w_lk : (proj == 1) ? w_rk
                    : (proj == 2) ? w_lv : w_rv;
    const float* Bv = (proj == 0) ? b_lk : (proj == 1) ? b_rk
                     : (proj == 2) ? b_lv : b_rv;

    for (int idx = tid; idx < 4096; idx += 256) {
        int p = idx >> 6, k = idx & 63;
        w_s[k * A_WS_STRIDE + p] = W[idx];
    }
    if (tid < 64) bias_s[tid] = Bv[tid];
    {
        const float4* src = (const float4*)(state + (size_t)rowBase * 64);
        float4* dst = (float4*)st_s;
        for (int i = tid; i < 1024; i += 256) dst[i] = src[i];
    }
    __syncthreads();

    const int p0 = (tid & 15) * 4;   // output column group
    const int r0 = (tid >> 4) * 4;   // row group

    float acc[4][4];
#pragma unroll
    for (int i = 0; i < 4; ++i)
#pragma unroll
        for (int j = 0; j < 4; ++j) acc[i][j] = 0.f;

#pragma unroll 8
    for (int k = 0; k < 64; ++k) {
        float4 wv = *(const float4*)&w_s[k * A_WS_STRIDE + p0];
#pragma unroll
        for (int i = 0; i < 4; ++i) {
            float s = st_s[(r0 + i) * 64 + k];
            acc[i][0] += s * wv.x;
            acc[i][1] += s * wv.y;
            acc[i][2] += s * wv.z;
            acc[i][3] += s * wv.w;
        }
    }

    const float4 bv = *(const float4*)&bias_s[p0];
    const int h  = p0 >> 4;
    const int d0 = p0 & 15;

#pragma unroll
    for (int i = 0; i < 4; ++i) {
        int row = rowBase + r0 + i;
        int b   = row / NNc;
        int idx = row - b * NNc;
        float v0 = acc[i][0] + bv.x;
        float v1 = acc[i][1] + bv.y;
        float v2 = acc[i][2] + bv.z;
        float v3 = acc[i][3] + bv.w;
        if (proj == 1) {
            // transposed: g_rkT[b][h][a][d][y]
            int a = idx / 96, y = idx - a * 96;
            size_t base = ((((size_t)(b * Hc + h) * Nc + a) * DKc + d0) * Nc) + y;
            g_rkT[base]          = v0;
            g_rkT[base + 96]     = v1;
            g_rkT[base + 192]    = v2;
            g_rkT[base + 288]    = v3;
        } else {
            size_t off = ((size_t)((proj * Bc + b) * Hc + h) * NNc + idx) * DKc + d0;
            float4 v; v.x = v0; v.y = v1; v.z = v2; v.w = v3;
            *(float4*)&g_proj[off] = v;
        }
    }
}

// ---------------------------------------------------------------------------
// Kernel B: scores + softmax(a) + triple-product contraction.
// Block per (b, h, x-tile of 3).  y in thirds of 32.
// Phase 2: coalesced rk via g_rkT, rk column cached in regs across tx.
// Phase 3: a-split 3 ways -> rv loaded exactly once; smem partial reduce.
// smem = 74.1 KB -> 3 blocks/SM, grid 256 -> single resident wave.
// ---------------------------------------------------------------------------
#define TXc 3
#define YHc 32

__global__ void __launch_bounds__(384, 3)
attn_kernel()
{
    extern __shared__ __align__(16) float smem[];
    float* lk_s = smem;                 // 4608 (overlaid by partials in ph.3)
    float* lv_s = smem + 4608;          // 4608
    float* sc   = smem + 9216;          // TX * 96 * 32 = 9216
    float* linv = smem + 18432;         // 96
    float* part = lk_s;                 // overlay: 9 * 128 * 4 = 4608 floats

    const int tid = threadIdx.x;
    const int xt = blockIdx.x % (Nc / TXc);
    const int bh = blockIdx.x / (Nc / TXc);
    const int h  = bh % Hc;
    const int b  = bh / Hc;
    const int x0 = xt * TXc;

    const int slab = NNc * DKc;  // 147456
    const float* lkbase = g_proj + (size_t)((0 * Bc + b) * Hc + h) * slab;
    const float* lvbase = g_proj + (size_t)((2 * Bc + b) * Hc + h) * slab;
    const float* rvbase = g_proj + (size_t)((3 * Bc + b) * Hc + h) * slab;
    const float* rkT    = g_rkT + (size_t)(b * Hc + h) * Nc * DKc * Nc;

    // load lv once (lives for whole kernel)
    {
        const float4* slv = (const float4*)(lvbase + (size_t)x0 * 1536);
        float4* dlv = (float4*)lv_s;
        for (int i = tid; i < 1152; i += 384) dlv[i] = slv[i];
    }

    for (int yh = 0; yh < 96; yh += YHc) {
        // (re)load lk (its smem is reused for partials each iteration)
        {
            const float4* slk = (const float4*)(lkbase + (size_t)x0 * 1536);
            float4* dlk = (float4*)lk_s;
            for (int i = tid; i < 1152; i += 384) dlk[i] = slk[i];
        }
        __syncthreads();

        // ---- Phase 2: lanes = y, warps stride over a. rk column in regs.
        {
            const int yl = tid & 31;
            const int w  = tid >> 5;          // 12 warps
            for (int a = w; a < 96; a += 12) {
                const float* rkp = rkT + (size_t)(a * 16) * 96 + yh + yl;
                float r[16];
#pragma unroll
                for (int d = 0; d < 16; ++d) r[d] = rkp[(size_t)d * 96];
#pragma unroll
                for (int tx = 0; tx < TXc; ++tx) {
                    const float4* lp = (const float4*)(lk_s + tx * 1536 + a * 16);
                    float4 l0 = lp[0], l1 = lp[1], l2 = lp[2], l3 = lp[3];
                    float s0 = l0.x * r[0]  + l0.y * r[1]  + l0.z * r[2]  + l0.w * r[3];
                    float s1 = l1.x * r[4]  + l1.y * r[5]  + l1.z * r[6]  + l1.w * r[7];
                    float s2 = l2.x * r[8]  + l2.y * r[9]  + l2.z * r[10] + l2.w * r[11];
                    float s3 = l3.x * r[12] + l3.y * r[13] + l3.z * r[14] + l3.w * r[15];
                    sc[tx * 3072 + a * 32 + yl] = (s0 + s1 + s2 + s3) * 0.25f;
                }
            }
        }
        __syncthreads();

        // ---- Softmax over a (unnormalized exp; keep 1/sum)
        if (tid < TXc * YHc) {
            int tx = tid >> 5;
            int yl = tid & 31;
            float* col = sc + tx * 3072 + yl;
            float m = -1e30f;
#pragma unroll 4
            for (int a = 0; a < 96; ++a) m = fmaxf(m, col[a * 32]);
            float l = 0.f;
#pragma unroll 4
            for (int a = 0; a < 96; ++a) {
                float e = __expf(col[a * 32] - m);
                col[a * 32] = e;
                l += e;
            }
            linv[tid] = 1.f / l;
        }
        __syncthreads();

        // ---- Phase 3: a-split accumulation, rv loaded once per (a,y,d)
        {
            const int dq = tid & 3;
            const int yl = (tid >> 2) & 31;
            const int as = tid >> 7;          // 0..2: a-chunk
            const int y  = yh + yl;
            float4 acc0 = {0,0,0,0}, acc1 = {0,0,0,0}, acc2 = {0,0,0,0};
            const int aEnd = as * 32 + 32;
#pragma unroll 4
            for (int a = as * 32; a < aEnd; ++a) {
                float4 rv = *(const float4*)(rvbase + (size_t)(a * 96 + y) * 16 + dq * 4);
                float w0 = sc[0 * 3072 + a * 32 + yl];
                float w1 = sc[1 * 3072 + a * 32 + yl];
                float w2 = sc[2 * 3072 + a * 32 + yl];
                float4 v0 = *(const float4*)(lv_s + 0 * 1536 + a * 16 + dq * 4);
                float4 v1 = *(const float4*)(lv_s + 1 * 1536 + a * 16 + dq * 4);
                float4 v2 = *(const float4*)(lv_s + 2 * 1536 + a * 16 + dq * 4);
                acc0.x += w0 * (v0.x * rv.x);  acc0.y += w0 * (v0.y * rv.y);
                acc0.z += w0 * (v0.z * rv.z);  acc0.w += w0 * (v0.w * rv.w);
                acc1.x += w1 * (v1.x * rv.x);  acc1.y += w1 * (v1.y * rv.y);
                acc1.z += w1 * (v1.z * rv.z);  acc1.w += w1 * (v1.w * rv.w);
                acc2.x += w2 * (v2.x * rv.x);  acc2.y += w2 * (v2.y * rv.y);
                acc2.z += w2 * (v2.z * rv.z);  acc2.w += w2 * (v2.w * rv.w);
            }
            // write partials: part[(as*3+tx)*128 + yl*4 + dq] (float4 units)
            float4* p4 = (float4*)part;
            p4[(as * 3 + 0) * 128 + yl * 4 + dq] = acc0;
            p4[(as * 3 + 1) * 128 + yl * 4 + dq] = acc1;
            p4[(as * 3 + 2) * 128 + yl * 4 + dq] = acc2;
        }
        __syncthreads();

        // ---- Reduce partials and store
        {
            const int tx = tid >> 7;          // 0..2
            const int rr = tid & 127;         // yl*4 + dq
            const int yl = rr >> 2;
            const int dq = rr & 3;
            const float4* p4 = (const float4*)part;
            float4 s0 = p4[(0 * 3 + tx) * 128 + rr];
            float4 s1 = p4[(1 * 3 + tx) * 128 + rr];
            float4 s2 = p4[(2 * 3 + tx) * 128 + rr];
            float sl = linv[tx * 32 + yl];
            float4 o;
            o.x = (s0.x + s1.x + s2.x) * sl;
            o.y = (s0.y + s1.y + s2.y) * sl;
            o.z = (s0.z + s1.z + s2.z) * sl;
            o.w = (s0.w + s1.w + s2.w) * sl;
            size_t row = (size_t)b * NNc + (size_t)(x0 + tx) * 96 + (yh + yl);
            *(float4*)&g_attout[row * 64 + h * 16 + dq * 4] = o;
        }
        __syncthreads();
    }
}

// ---------------------------------------------------------------------------
// Kernel C: output projection.  out[i][p] = attout[i][:] @ w_out^T + b_out
// ---------------------------------------------------------------------------
#define C_WS_STRIDE 68

__global__ void __launch_bounds__(256)
out_kernel(const float* __restrict__ w_out, const float* __restrict__ b_out,
           float* __restrict__ out)
{
    __shared__ __align__(16) float w_s[64 * C_WS_STRIDE];
    __shared__ __align__(16) float st_s[64 * 64];
    __shared__ float bias_s[64];

    const int tid = threadIdx.x;
    const int rowBase = blockIdx.x * 64;

    for (int idx = tid; idx < 4096; idx += 256) {
        int p = idx >> 6, k = idx & 63;
        w_s[k * C_WS_STRIDE + p] = w_out[idx];
    }
    if (tid < 64) bias_s[tid] = b_out[tid];
    {
        const float4* src = (const float4*)(g_attout + (size_t)rowBase * 64);
        float4* dst = (float4*)st_s;
        for (int i = tid; i < 1024; i += 256) dst[i] = src[i];
    }
    __syncthreads();

    const int p0 = (tid & 15) * 4;
    const int r0 = (tid >> 4) * 4;

    float acc[4][4];
#pragma unroll
    for (int i = 0; i < 4; ++i)
#pragma unroll
        for (int j = 0; j < 4; ++j) acc[i][j] = 0.f;

#pragma unroll 8
    for (int k = 0; k < 64; ++k) {
        float4 wv = *(const float4*)&w_s[k * C_WS_STRIDE + p0];
#pragma unroll
        for (int i = 0; i < 4; ++i) {
            float s = st_s[(r0 + i) * 64 + k];
            acc[i][0] += s * wv.x;
            acc[i][1] += s * wv.y;
            acc[i][2] += s * wv.z;
            acc[i][3] += s * wv.w;
        }
    }

    const float4 bv = *(const float4*)&bias_s[p0];
#pragma unroll
    for (int i = 0; i < 4; ++i) {
        int row = rowBase + r0 + i;
        float4 v;
        v.x = acc[i][0] + bv.x;
        v.y = acc[i][1] + bv.y;
        v.z = acc[i][2] + bv.z;
        v.w = acc[i][3] + bv.w;
        *(float4*)&out[(size_t)row * 64 + p0] = v;
    }
}

// ---------------------------------------------------------------------------
extern "C" void kernel_launch(void* const* d_in, const int* in_sizes, int n_in,
                              void* d_out, int out_size)
{
    const float* state = (const float*)d_in[0];
    const float* w_lk = (const float*)d_in[1];
    const float* b_lk = (const float*)d_in[2];
    const float* w_rk = (const float*)d_in[3];
    const float* b_rk = (const float*)d_in[4];
    const float* w_lv = (const float*)d_in[5];
    const float* b_lv = (const float*)d_in[6];
    const float* w_rv = (const float*)d_in[7];
    const float* b_rv = (const float*)d_in[8];
    const float* w_out = (const float*)d_in[9];
    const float* b_out = (const float*)d_in[10];
    float* out = (float*)d_out;

    const int smemB = (4608 + 4608 + 9216 + 96) * 4;  // 74112 B

    static bool attr_done = false;
    if (!attr_done) {
        cudaFuncSetAttribute(attn_kernel,
                             cudaFuncAttributeMaxDynamicSharedMemorySize, smemB);
        attr_done = true;
    }

    dim3 gridA(ROWS_TOTAL / 64, 4);
    proj_kernel<<<gridA, 256>>>(
        state, w_lk, b_lk, w_rk, b_rk, w_lv, b_lv, w_rv, b_rv);

    attn_kernel<<<Bc * Hc * (Nc / TXc), 384, smemB>>>();

    out_kernel<<<ROWS_TOTAL / 64, 256>>>(w_out, b_out, out);
}